// round 8
// baseline (speedup 1.0000x reference)
#include <cuda_runtime.h>
#include <math_constants.h>

// Prefix-max (cumulative max) along H for x of shape (B=32, C=1, H=1024, W=1024), fp32.
// Layout: x[(b*H + h)*W + w]. 32768 independent columns (b,w), scan length H=1024.
//
// Geometry: 256-thread block owns 16 consecutive float-columns x full H
// (grid 2048, 64B warp segments — the proven-best access pattern), at
// 8 CTAs/SM (__launch_bounds__(256, 8), regs <= 32). 1184 concurrent CTAs
// -> 2048 tiles run as 1184 + 864: both waves >= 5.8 CTAs/SM, eliminating
// the skinny tail wave that capped previous rounds.
//   thread t: c = t & 15, chunk = t >> 4 (16 chunks of 8 rows per pass).
//   8 passes over H. Per pass: coalesced loads, local prefix-max, chunk
//   totals -> smem (1 barrier), warp scans 2 columns via width-16 shuffles
//   (4 rounds, no barrier), read-back (1 barrier), apply carry, stores.
// Double-buffered smem: 2 barriers per pass, 16 total.

#define H_DIM 1024
#define W_DIM 1024
#define COLS_PER_BLOCK 16
#define CHUNKS 16
#define ROWS_PER_THREAD 8     // per pass
#define PASS_ROWS 128         // CHUNKS * ROWS_PER_THREAD
#define NUM_PASSES 8

__global__ __launch_bounds__(256, 8)
void cummax_kernel(const float* __restrict__ x, float* __restrict__ out) {
    const int tid   = threadIdx.x;
    const int c     = tid & (COLS_PER_BLOCK - 1);   // 0..15
    const int chunk = tid >> 4;                     // 0..15
    const int wid   = tid >> 5;                     // 0..7
    const int lane  = tid & 31;

    const int col = blockIdx.x * COLS_PER_BLOCK + c;  // 1024 % 16 == 0: no b straddle
    const int b   = col >> 10;
    const int w   = col & (W_DIM - 1);

    const int base0 = b * (H_DIM * W_DIM) + w + chunk * ROWS_PER_THREAD * W_DIM;

    __shared__ float s[2][CHUNKS][COLS_PER_BLOCK + 1];   // double buffer, padded

    // Warp-scan mapping: warp `wid` scans columns 2*wid and 2*wid+1;
    // lanes 0-15 hold chunks 0-15 of col 2*wid, lanes 16-31 of col 2*wid+1.
    const int scan_col = 2 * wid + (lane >> 4);
    const int scan_ch  = lane & 15;

    float carry = -CUDART_INF_F;

#pragma unroll
    for (int p = 0; p < NUM_PASSES; p++) {
        const int buf  = p & 1;
        const int base = base0 + p * PASS_ROWS * W_DIM;
        const float* __restrict__ src = x   + base;
        float*       __restrict__ dst = out + base;

        // Load 8 rows (coalesced: warp covers 2 rows x 64B fully-used segments).
        float v[ROWS_PER_THREAD];
#pragma unroll
        for (int i = 0; i < ROWS_PER_THREAD; i++) {
            v[i] = src[i * W_DIM];
        }
#pragma unroll
        for (int i = 1; i < ROWS_PER_THREAD; i++) {
            v[i] = fmaxf(v[i], v[i - 1]);
        }

        // Cross-chunk inclusive max-scan of totals via width-16 warp shuffles.
        s[buf][chunk][c] = v[ROWS_PER_THREAD - 1];
        __syncthreads();

        {
            float t = s[buf][scan_ch][scan_col];
#pragma unroll
            for (int d = 1; d < 16; d <<= 1) {
                float o = __shfl_up_sync(0xFFFFFFFFu, t, d, 16);
                if (scan_ch >= d) t = fmaxf(t, o);
            }
            s[buf][scan_ch][scan_col] = t;
        }
        __syncthreads();

        // Exclusive carry: preceding chunks of this pass + previous passes.
        const float excl = (chunk > 0) ? s[buf][chunk - 1][c] : -CUDART_INF_F;
        const float m = fmaxf(carry, excl);

#pragma unroll
        for (int i = 0; i < ROWS_PER_THREAD; i++) {
            dst[i * W_DIM] = fmaxf(v[i], m);
        }

        carry = fmaxf(carry, s[buf][CHUNKS - 1][c]);
    }
}

extern "C" void kernel_launch(void* const* d_in, const int* in_sizes, int n_in,
                              void* d_out, int out_size) {
    const float* x = (const float*)d_in[0];
    float* out = (float*)d_out;

    const int total_cols = 32 * W_DIM;                        // 32768
    const int grid = total_cols / COLS_PER_BLOCK;             // 2048
    cummax_kernel<<<grid, 256>>>(x, out);
}